// round 15
// baseline (speedup 1.0000x reference)
#include <cuda_runtime.h>
#include <cuda_bf16.h>
#include <cstring>
#include <cstdint>

#define TLEN   4096
#define DMODEL 1024
#define NHEADS 16
#define HDIM   64

// ---------------- device scratch ----------------
__device__ __nv_bfloat16 g_xh[TLEN * DMODEL], g_xl[TLEN * DMODEL];
__device__ __nv_bfloat16 g_wh[4 * DMODEL * DMODEL], g_wl[4 * DMODEL * DMODEL];
__device__ __nv_bfloat16 g_qh[NHEADS * TLEN * HDIM], g_ql[NHEADS * TLEN * HDIM];
__device__ __nv_bfloat16 g_kh[NHEADS * TLEN * HDIM], g_kl[NHEADS * TLEN * HDIM];
__device__ __nv_bfloat16 g_vh[NHEADS * TLEN * HDIM], g_vl[NHEADS * TLEN * HDIM];
__device__ __nv_bfloat16 g_oh[TLEN * DMODEL], g_ol[TLEN * DMODEL];

// ---------------- fastexp fused form ----------------
__device__ __forceinline__ float fexp_fused(float s, float gas, float crow) {
    float y = __fmaf_rn(s, gas, crow);
    int yi = (y < 8388608.0f) ? 0 : __float2int_rz(y);
    return __int_as_float(yi);
}

// ---------------- helpers ----------------
__device__ __forceinline__ uint32_t sptr(const void* p) {
    return (uint32_t)__cvta_generic_to_shared(p);
}
__device__ __forceinline__ void ldsm4(uint32_t a, uint32_t* r) {
    asm volatile("ldmatrix.sync.aligned.m8n8.x4.shared.b16 {%0,%1,%2,%3}, [%4];"
                 : "=r"(r[0]), "=r"(r[1]), "=r"(r[2]), "=r"(r[3]) : "r"(a));
}
__device__ __forceinline__ void ldsm4t(uint32_t a, uint32_t* r) {
    asm volatile("ldmatrix.sync.aligned.m8n8.x4.trans.shared.b16 {%0,%1,%2,%3}, [%4];"
                 : "=r"(r[0]), "=r"(r[1]), "=r"(r[2]), "=r"(r[3]) : "r"(a));
}
__device__ __forceinline__ void mma16816(float* c, const uint32_t* a,
                                         uint32_t b0, uint32_t b1) {
    asm volatile(
        "mma.sync.aligned.m16n8k16.row.col.f32.bf16.bf16.f32 "
        "{%0,%1,%2,%3}, {%4,%5,%6,%7}, {%8,%9}, {%0,%1,%2,%3};"
        : "+f"(c[0]), "+f"(c[1]), "+f"(c[2]), "+f"(c[3])
        : "r"(a[0]), "r"(a[1]), "r"(a[2]), "r"(a[3]), "r"(b0), "r"(b1));
}
__device__ __forceinline__ int sw128B(int row, int ch) {
    return (row << 7) + ((ch ^ (row & 7)) << 4);
}
// fast split: packed bf16x2 cvt
__device__ __forceinline__ void split2(float v0, float v1, uint32_t& ph, uint32_t& pl) {
    uint32_t h;
    asm("cvt.rn.bf16x2.f32 %0, %1, %2;" : "=r"(h) : "f"(v1), "f"(v0));
    float h0 = __uint_as_float(h << 16);
    float h1 = __uint_as_float(h & 0xffff0000u);
    uint32_t l;
    float r0 = v0 - h0, r1 = v1 - h1;
    asm("cvt.rn.bf16x2.f32 %0, %1, %2;" : "=r"(l) : "f"(r1), "f"(r0));
    ph = h; pl = l;
}
__device__ __forceinline__ uint32_t pack_bf16x2(float v0, float v1) {
    uint32_t h;
    asm("cvt.rn.bf16x2.f32 %0, %1, %2;" : "=r"(h) : "f"(v1), "f"(v0));
    return h;
}
// cp.async
__device__ __forceinline__ void cp16(uint32_t s, const void* g) {
    asm volatile("cp.async.cg.shared.global [%0], [%1], 16;" :: "r"(s), "l"(g));
}
#define CP_COMMIT() asm volatile("cp.async.commit_group;" ::: "memory")
#define CP_WAIT(n)  asm volatile("cp.async.wait_group %0;" :: "n"(n) : "memory")

// ---------------- fused split (fp32 -> bf16 hi/lo), float4-vectorized -------
__global__ void split_all(const float* __restrict__ x, const float* __restrict__ wq,
                          const float* __restrict__ wk, const float* __restrict__ wv,
                          const float* __restrict__ wo) {
    const int total4 = (TLEN * DMODEL + 4 * DMODEL * DMODEL) >> 2;
    for (int i4 = blockIdx.x * blockDim.x + threadIdx.x; i4 < total4;
         i4 += gridDim.x * blockDim.x) {
        int i = i4 << 2;
        const float* src;
        __nv_bfloat16 *hi, *lo;
        int off;
        if (i < TLEN * DMODEL) {
            src = x; hi = g_xh; lo = g_xl; off = i;
        } else {
            int j = i - TLEN * DMODEL;
            int w = j >> 20;
            off = j & ((1 << 20) - 1);
            src = (w == 0) ? wq : (w == 1) ? wk : (w == 2) ? wv : wo;
            hi = g_wh + ((size_t)w << 20);
            lo = g_wl + ((size_t)w << 20);
        }
        float4 v = *(const float4*)(src + off);
        uint32_t h0, l0, h1, l1;
        split2(v.x, v.y, h0, l0);
        split2(v.z, v.w, h1, l1);
        *(uint2*)(hi + off) = make_uint2(h0, h1);
        *(uint2*)(lo + off) = make_uint2(l0, l1);
    }
}

// ============================================================================
// Split-bf16 mma.sync GEMM (KC=64, 3-stage cp.async, 1 sync per chunk).
// Prefetch for kc+2 issues RIGHT AFTER the sync (before compute) — the sync
// proves stage (kc+2)%3's readers (iteration kc-1) are done.
// ============================================================================
#define GEMM_SMEM 196608

__device__ __forceinline__ void gemm_prefetch(uint32_t sb, int s, int kc,
                                              const __nv_bfloat16* Ah, const __nv_bfloat16* Al,
                                              const __nv_bfloat16* Wh, const __nv_bfloat16* Wl,
                                              int m0, int n0, int tid) {
    uint32_t base = sb + s * 65536;
    #pragma unroll
    for (int p = 0; p < 4; p++) {
        int idx = p * 256 + tid;
        int r = idx >> 3, ch = idx & 7;
        size_t ga = (size_t)(m0 + r) * DMODEL + kc * 64 + ch * 8;
        size_t gw = (size_t)(n0 + r) * DMODEL + kc * 64 + ch * 8;
        uint32_t so = sw128B(r, ch);
        cp16(base + so,          Ah + ga);
        cp16(base + 16384 + so,  Al + ga);
        cp16(base + 32768 + so,  Wh + gw);
        cp16(base + 49152 + so,  Wl + gw);
    }
}

__global__ __launch_bounds__(256, 1)
void gemm_bf16(int a_sel, int w_fixed, const float* __restrict__ bq,
               const float* __restrict__ bk, const float* __restrict__ bv,
               float* __restrict__ dout)
{
    extern __shared__ char sm[];
    uint32_t sb = sptr(sm);
    const int c_sel = (w_fixed < 0) ? (int)blockIdx.z : 3;
    const int w_idx = (w_fixed < 0) ? (int)blockIdx.z : w_fixed;
    const float* bias = (c_sel == 0) ? bq : (c_sel == 1) ? bk : (c_sel == 2) ? bv : nullptr;

    const __nv_bfloat16* Ah = a_sel ? g_oh : g_xh;
    const __nv_bfloat16* Al = a_sel ? g_ol : g_xl;
    const __nv_bfloat16* Wh = g_wh + (size_t)w_idx * DMODEL * DMODEL;
    const __nv_bfloat16* Wl = g_wl + (size_t)w_idx * DMODEL * DMODEL;

    const int tid = threadIdx.x;
    const int lane = tid & 31, wid = tid >> 5;
    const int g = lane >> 2, tg = lane & 3;
    const int wm = wid >> 2, wn = wid & 3;
    const int m0 = blockIdx.y * 128, n0 = blockIdx.x * 128;

    float c[4][4][4];
    #pragma unroll
    for (int i = 0; i < 4; i++)
        #pragma unroll
        for (int j = 0; j < 4; j++)
            #pragma unroll
            for (int e = 0; e < 4; e++) c[i][j][e] = 0.f;

    gemm_prefetch(sb, 0, 0, Ah, Al, Wh, Wl, m0, n0, tid);
    CP_COMMIT();
    gemm_prefetch(sb, 1, 1, Ah, Al, Wh, Wl, m0, n0, tid);
    CP_COMMIT();

    const int ar = lane & 15;
    const int br = ((lane >> 4) << 3) + (lane & 7);

    for (int kc = 0; kc < 16; kc++) {
        int s = kc % 3;
        if (kc < 15) { CP_WAIT(1); } else { CP_WAIT(0); }
        __syncthreads();

        // prefetch-early: issue kc+2 before compute (readers of that stage done)
        if (kc + 2 < 16) {
            gemm_prefetch(sb, (kc + 2) % 3, kc + 2, Ah, Al, Wh, Wl, m0, n0, tid);
            CP_COMMIT();
        }

        uint32_t sAh = sb + s * 65536;
        uint32_t sAl = sAh + 16384;
        uint32_t sWh = sAh + 32768;
        uint32_t sWl = sAh + 49152;

        #pragma unroll
        for (int kt = 0; kt < 4; kt++) {
            uint32_t ah[4][4], al[4][4];
            const int ac = kt * 2 + (lane >> 4);
            #pragma unroll
            for (int mi = 0; mi < 4; mi++) {
                int r = wm * 64 + mi * 16 + ar;
                int off = sw128B(r, ac);
                ldsm4(sAh + off, ah[mi]);
                ldsm4(sAl + off, al[mi]);
            }
            uint32_t bh[2][4], bl[2][4];
            const int bc = kt * 2 + ((lane >> 3) & 1);
            #pragma unroll
            for (int pr = 0; pr < 2; pr++) {
                int r = wn * 32 + pr * 16 + br;
                int off = sw128B(r, bc);
                ldsm4(sWh + off, bh[pr]);
                ldsm4(sWl + off, bl[pr]);
            }
            #pragma unroll
            for (int mi = 0; mi < 4; mi++)
                #pragma unroll
                for (int ni = 0; ni < 4; ni++) {
                    uint32_t b0h = bh[ni >> 1][(ni & 1) * 2], b1h = bh[ni >> 1][(ni & 1) * 2 + 1];
                    uint32_t b0l = bl[ni >> 1][(ni & 1) * 2], b1l = bl[ni >> 1][(ni & 1) * 2 + 1];
                    mma16816(c[mi][ni], ah[mi], b0h, b1h);
                    mma16816(c[mi][ni], ah[mi], b0l, b1l);
                    mma16816(c[mi][ni], al[mi], b0h, b1h);
                }
        }
    }

    __nv_bfloat16 *dsth = nullptr, *dstl = nullptr;
    if (c_sel == 0) { dsth = g_qh; dstl = g_ql; }
    else if (c_sel == 1) { dsth = g_kh; dstl = g_kl; }
    else if (c_sel == 2) { dsth = g_vh; dstl = g_vl; }

    #pragma unroll
    for (int mi = 0; mi < 4; mi++)
        #pragma unroll
        for (int ni = 0; ni < 4; ni++)
            #pragma unroll
            for (int inst = 0; inst < 2; inst++) {
                int m = m0 + wm * 64 + mi * 16 + inst * 8 + g;
                int n = n0 + wn * 32 + ni * 8 + 2 * tg;
                float b0 = bias ? bias[n] : 0.f;
                float b1 = bias ? bias[n + 1] : 0.f;
                float v0 = c[mi][ni][inst * 2] + b0;
                float v1 = c[mi][ni][inst * 2 + 1] + b1;
                if (c_sel < 3) {
                    uint32_t ph, pl;
                    split2(v0, v1, ph, pl);
                    size_t addr = ((size_t)(n >> 6) * TLEN + m) * HDIM + (n & 63);
                    *(uint32_t*)(dsth + addr) = ph;
                    *(uint32_t*)(dstl + addr) = pl;
                } else {
                    float2 r; r.x = v0; r.y = v1;
                    *(float2*)(dout + (size_t)m * DMODEL + n) = r;
                }
            }
}

// ============================================================================
// Warp-strip attention v6: 256 threads (8 warps), warp owns 32 q-rows.
// 128-key tiles, 3-stage cp.async, prefetch-early, pipelined exp+PV.
// SMEM stage (64KB): KH +0 | KL +16K | VH +32K | VL +48K. Total 192KB.
// ============================================================================
#define AT_S(s)  ((s) * 65536)
#define ATTN_SMEM 196608
#define NT128    32

__device__ __forceinline__ void cp_tile128(uint32_t sdst, const __nv_bfloat16* g, int tid) {
    #pragma unroll
    for (int p = 0; p < 4; p++) {
        int idx = p * 256 + tid;
        int r = idx >> 3, ch = idx & 7;
        cp16(sdst + sw128B(r, ch), g + (size_t)r * HDIM + ch * 8);
    }
}
__device__ __forceinline__ void cp_tile256(uint32_t sdst, const __nv_bfloat16* g, int tid) {
    #pragma unroll
    for (int p = 0; p < 8; p++) {
        int idx = p * 256 + tid;
        int r = idx >> 3, ch = idx & 7;
        cp16(sdst + sw128B(r, ch), g + (size_t)r * HDIM + ch * 8);
    }
}

__global__ __launch_bounds__(256, 1)
void attn_kernel(float scaling)
{
    extern __shared__ char sm[];
    uint32_t sb = sptr(sm);
    const int tid = threadIdx.x;
    const int lane = tid & 31, wid = tid >> 5;
    const int tg = lane & 3;
    const int h = blockIdx.y;
    const int t0 = blockIdx.x * 256;

    const float GA = (float)12102203.17133801;
    const float GB = (float)1064986823.010288;
    const float GAS = __fmul_rn(GA, scaling);

    const __nv_bfloat16* Kh  = g_kh + (size_t)h * TLEN * HDIM;
    const __nv_bfloat16* Klp = g_kl + (size_t)h * TLEN * HDIM;
    const __nv_bfloat16* Vh  = g_vh + (size_t)h * TLEN * HDIM;
    const __nv_bfloat16* Vlp = g_vl + (size_t)h * TLEN * HDIM;

    const int ar = lane & 15;
    const int br = ((lane >> 4) << 3) + (lane & 7);

    // ---- Q into stage-0 alias, hoist fragments, then free ----
    cp_tile256(sb + 0,     g_qh + ((size_t)h * TLEN + t0) * HDIM, tid);
    cp_tile256(sb + 32768, g_ql + ((size_t)h * TLEN + t0) * HDIM, tid);
    CP_COMMIT();
    CP_WAIT(0);
    __syncthreads();
    uint32_t qh[2][4][4], ql[2][4][4];
    #pragma unroll
    for (int mi = 0; mi < 2; mi++)
        #pragma unroll
        for (int kt = 0; kt < 4; kt++) {
            int ac = kt * 2 + (lane >> 4);
            int r = wid * 32 + mi * 16 + ar;
            ldsm4(sb + 0     + sw128B(r, ac), qh[mi][kt]);
            ldsm4(sb + 32768 + sw128B(r, ac), ql[mi][kt]);
        }
    __syncthreads();

    cp_tile128(sb + AT_S(0), Kh, tid);
    CP_COMMIT();
    cp_tile128(sb + AT_S(1), Kh + (size_t)128 * HDIM, tid);
    CP_COMMIT();

    // =================== pass 1: rowmax on RAW scores ===================
    float rm[2][2];
    #pragma unroll
    for (int mi = 0; mi < 2; mi++) { rm[mi][0] = -3.402823466e38f; rm[mi][1] = -3.402823466e38f; }

    for (int st = 0; st < NT128; st++) {
        if (st < NT128 - 1) { CP_WAIT(1); } else { CP_WAIT(0); }
        __syncthreads();
        if (st + 2 < NT128) {
            cp_tile128(sb + AT_S((st + 2) % 3), Kh + (size_t)(st + 2) * 128 * HDIM, tid);
            CP_COMMIT();
        }
        uint32_t sKh = sb + AT_S(st % 3);

        #pragma unroll
        for (int n2 = 0; n2 < 8; n2++) {
            float c[2][2][4];
            #pragma unroll
            for (int mi = 0; mi < 2; mi++)
                #pragma unroll
                for (int u = 0; u < 2; u++)
                    #pragma unroll
                    for (int e = 0; e < 4; e++) c[mi][u][e] = 0.f;
            #pragma unroll
            for (int kt = 0; kt < 4; kt++) {
                uint32_t bh[4];
                ldsm4(sKh + sw128B(n2 * 16 + br, kt * 2 + ((lane >> 3) & 1)), bh);
                #pragma unroll
                for (int mi = 0; mi < 2; mi++) {
                    mma16816(c[mi][0], qh[mi][kt], bh[0], bh[1]);
                    mma16816(c[mi][1], qh[mi][kt], bh[2], bh[3]);
                }
            }
            #pragma unroll
            for (int mi = 0; mi < 2; mi++)
                #pragma unroll
                for (int u = 0; u < 2; u++) {
                    rm[mi][0] = fmaxf(rm[mi][0], fmaxf(c[mi][u][0], c[mi][u][1]));
                    rm[mi][1] = fmaxf(rm[mi][1], fmaxf(c[mi][u][2], c[mi][u][3]));
                }
        }
    }
    float cr[2][2];
    #pragma unroll
    for (int mi = 0; mi < 2; mi++)
        #pragma unroll
        for (int i = 0; i < 2; i++) {
            float v = rm[mi][i];
            v = fmaxf(v, __shfl_xor_sync(0xffffffff, v, 1));
            v = fmaxf(v, __shfl_xor_sync(0xffffffff, v, 2));
            float rmx = __fmul_rn(v, scaling);
            cr[mi][i] = __fmaf_rn(-GA, rmx, GB);
        }

    // =================== pass 2: pipelined exp + PV ===================
    float o[2][8][4];
    #pragma unroll
    for (int mi = 0; mi < 2; mi++)
        #pragma unroll
        for (int i = 0; i < 8; i++)
            #pragma unroll
            for (int e = 0; e < 4; e++) o[mi][i][e] = 0.f;
    float rs[2][2] = {{0.f, 0.f}, {0.f, 0.f}};

    __syncthreads();
    #pragma unroll
    for (int t = 0; t < 2; t++) {
        size_t go = (size_t)t * 128 * HDIM;
        uint32_t d = sb + AT_S(t);
        cp_tile128(d,         Kh + go, tid);
        cp_tile128(d + 16384, Klp + go, tid);
        cp_tile128(d + 32768, Vh + go, tid);
        cp_tile128(d + 49152, Vlp + go, tid);
        CP_COMMIT();
    }

    for (int st = 0; st < NT128; st++) {
        if (st < NT128 - 1) { CP_WAIT(1); } else { CP_WAIT(0); }
        __syncthreads();
        if (st + 2 < NT128) {
            size_t go = (size_t)(st + 2) * 128 * HDIM;
            uint32_t d = sb + AT_S((st + 2) % 3);
            cp_tile128(d,         Kh + go, tid);
            cp_tile128(d + 16384, Klp + go, tid);
            cp_tile128(d + 32768, Vh + go, tid);
            cp_tile128(d + 49152, Vlp + go, tid);
            CP_COMMIT();
        }

        uint32_t base = sb + AT_S(st % 3);
        uint32_t sKh = base, sKl = base + 16384;
        uint32_t sVh = base + 32768, sVl = base + 49152;

        uint32_t ehp[2][4];

        #pragma unroll
        for (int n2 = 0; n2 < 8; n2++) {
            float c[2][2][4];
            #pragma unroll
            for (int mi = 0; mi < 2; mi++)
                #pragma unroll
                for (int u = 0; u < 2; u++)
                    #pragma unroll
                    for (int e = 0; e < 4; e++) c[mi][u][e] = 0.f;
            #pragma unroll
            for (int kt = 0; kt < 4; kt++) {
                uint32_t bh[4], bl[4];
                int soff = sw128B(n2 * 16 + br, kt * 2 + ((lane >> 3) & 1));
                ldsm4(sKh + soff, bh);
                ldsm4(sKl + soff, bl);
                #pragma unroll
                for (int mi = 0; mi < 2; mi++) {
                    mma16816(c[mi][0], qh[mi][kt], bh[0], bh[1]);
                    mma16816(c[mi][0], qh[mi][kt], bl[0], bl[1]);
                    mma16816(c[mi][0], ql[mi][kt], bh[0], bh[1]);
                    mma16816(c[mi][1], qh[mi][kt], bh[2], bh[3]);
                    mma16816(c[mi][1], qh[mi][kt], bl[2], bl[3]);
                    mma16816(c[mi][1], ql[mi][kt], bh[2], bh[3]);
                }
            }

            if (n2 > 0) {
                int pv = n2 - 1;
                #pragma unroll
                for (int dg = 0; dg < 4; dg++) {
                    uint32_t vh[4], vl[4];
                    int voff = sw128B(pv * 16 + ar, dg * 2 + (lane >> 4));
                    ldsm4t(sVh + voff, vh);
                    ldsm4t(sVl + voff, vl);
                    #pragma unroll
                    for (int mi = 0; mi < 2; mi++) {
                        mma16816(o[mi][dg * 2],     ehp[mi], vh[0], vh[1]);
                        mma16816(o[mi][dg * 2],     ehp[mi], vl[0], vl[1]);
                        mma16816(o[mi][dg * 2 + 1], ehp[mi], vh[2], vh[3]);
                        mma16816(o[mi][dg * 2 + 1], ehp[mi], vl[2], vl[3]);
                    }
                }
            }

            #pragma unroll
            for (int mi = 0; mi < 2; mi++) {
                float e00 = fexp_fused(c[mi][0][0], GAS, cr[mi][0]);
                float e01 = fexp_fused(c[mi][0][1], GAS, cr[mi][0]);
                float e02 = fexp_fused(c[mi][0][2], GAS, cr[mi][1]);
                float e03 = fexp_fused(c[mi][0][3], GAS, cr[mi][1]);
                float e10 = fexp_fused(c[mi][1][0], GAS, cr[mi][0]);
                float e11 = fexp_fused(c[mi][1][1], GAS, cr[mi][0]);
                float e12 = fexp_fused(c[mi][1][2], GAS, cr[mi][1]);
                float e13 = fexp_fused(c[mi][1][3], GAS, cr[mi][1]);
                rs[mi][0] += e00 + e01 + e10 + e11;
                rs[mi][1] += e02 + e03 + e12 + e13;
                ehp[mi][0] = pack_bf16x2(e00, e01);
                ehp[mi][1] = pack_bf16x2(e02, e03);
                ehp[mi][2] = pack_bf16x2(e10, e11);
                ehp[mi][3] = pack_bf16x2(e12, e13);
            }
        }

        #pragma unroll
        for (int dg = 0; dg < 4; dg++) {
            uint32_t vh[4], vl[4];
            int voff = sw128B(7 * 16 + ar, dg * 2 + (lane >> 4));
            ldsm4t(sVh + voff, vh);
            ldsm4t(sVl + voff, vl);
            #pragma unroll
            for (int mi = 0; mi < 2; mi++) {
                mma16816(o[mi][dg * 2],     ehp[mi], vh[0], vh[1]);
                mma16816(o[mi][dg * 2],     ehp[mi], vl[0], vl[1]);
                mma16816(o[mi][dg * 2 + 1], ehp[mi], vh[2], vh[3]);
                mma16816(o[mi][dg * 2 + 1], ehp[mi], vl[2], vl[3]);
            }
        }
    }

    // ---- rowsum reduce + normalize + split-store O ----
    #pragma unroll
    for (int mi = 0; mi < 2; mi++) {
        #pragma unroll
        for (int i = 0; i < 2; i++) {
            rs[mi][i] += __shfl_xor_sync(0xffffffff, rs[mi][i], 1);
            rs[mi][i] += __shfl_xor_sync(0xffffffff, rs[mi][i], 2);
        }
        float inv0 = 1.0f / rs[mi][0], inv1 = 1.0f / rs[mi][1];
        int r0 = t0 + wid * 32 + mi * 16 + (lane >> 2);
        #pragma unroll
        for (int dn = 0; dn < 8; dn++) {
            int d = h * HDIM + dn * 8 + 2 * tg;
            uint32_t ph, pl;
            split2(o[mi][dn][0] * inv0, o[mi][dn][1] * inv0, ph, pl);
            *(uint32_t*)(g_oh + (size_t)r0 * DMODEL + d) = ph;
            *(uint32_t*)(g_ol + (size_t)r0 * DMODEL + d) = pl;
            split2(o[mi][dn][2] * inv1, o[mi][dn][3] * inv1, ph, pl);
            *(uint32_t*)(g_oh + (size_t)(r0 + 8) * DMODEL + d) = ph;
            *(uint32_t*)(g_ol + (size_t)(r0 + 8) * DMODEL + d) = pl;
        }
    }
}

// ============================================================================
extern "C" void kernel_launch(void* const* d_in, const int* in_sizes, int n_in,
                              void* d_out, int out_size)
{
    const float* x  = (const float*)d_in[0];
    const float* Wq = (const float*)d_in[1];
    const float* bq = (const float*)d_in[2];
    const float* Wk = (const float*)d_in[3];
    const float* bk = (const float*)d_in[4];
    const float* Wv = (const float*)d_in[5];
    const float* bv = (const float*)d_in[6];
    const float* Wo = (const float*)d_in[7];
    float* out = (float*)d_out;

    // Quake q_rsqrt(64) exact fp32 step order
    float xq = 64.0f;
    int ib;
    memcpy(&ib, &xq, 4);
    ib = 0x5f3759df - (ib >> 1);
    float y;
    memcpy(&y, &ib, 4);
    float t = 0.5f * xq;
    t = t * y;
    t = t * y;
    float scaling = y * (1.5f - t);

    cudaFuncSetAttribute(gemm_bf16, cudaFuncAttributeMaxDynamicSharedMemorySize, GEMM_SMEM);
    cudaFuncSetAttribute(attn_kernel, cudaFuncAttributeMaxDynamicSharedMemorySize, ATTN_SMEM);

    split_all<<<2048, 256>>>(x, Wq, Wk, Wv, Wo);

    dim3 qkv_grid(DMODEL / 128, TLEN / 128, 3);
    gemm_bf16<<<qkv_grid, 256, GEMM_SMEM>>>(0, -1, bq, bk, bv, out);

    attn_kernel<<<dim3(TLEN / 256, NHEADS), 256, ATTN_SMEM>>>(scaling);

    dim3 o_grid(DMODEL / 128, TLEN / 128, 1);
    gemm_bf16<<<o_grid, 256, GEMM_SMEM>>>(1, 3, nullptr, nullptr, nullptr, out);
}

// round 16
// speedup vs baseline: 1.0081x; 1.0081x over previous
#include <cuda_runtime.h>
#include <cuda_bf16.h>
#include <cstring>
#include <cstdint>

#define TLEN   4096
#define DMODEL 1024
#define NHEADS 16
#define HDIM   64

// ---------------- device scratch ----------------
__device__ __nv_bfloat16 g_xh[TLEN * DMODEL], g_xl[TLEN * DMODEL];
__device__ __nv_bfloat16 g_wh[4 * DMODEL * DMODEL], g_wl[4 * DMODEL * DMODEL];
__device__ __nv_bfloat16 g_qh[NHEADS * TLEN * HDIM], g_ql[NHEADS * TLEN * HDIM];
__device__ __nv_bfloat16 g_kh[NHEADS * TLEN * HDIM], g_kl[NHEADS * TLEN * HDIM];
__device__ __nv_bfloat16 g_vh[NHEADS * TLEN * HDIM], g_vl[NHEADS * TLEN * HDIM];
__device__ __nv_bfloat16 g_oh[TLEN * DMODEL], g_ol[TLEN * DMODEL];

// ---------------- fastexp fused form ----------------
__device__ __forceinline__ float fexp_fused(float s, float gas, float crow) {
    float y = __fmaf_rn(s, gas, crow);
    int yi = (y < 8388608.0f) ? 0 : __float2int_rz(y);
    return __int_as_float(yi);
}

// ---------------- helpers ----------------
__device__ __forceinline__ uint32_t sptr(const void* p) {
    return (uint32_t)__cvta_generic_to_shared(p);
}
__device__ __forceinline__ void ldsm4(uint32_t a, uint32_t* r) {
    asm volatile("ldmatrix.sync.aligned.m8n8.x4.shared.b16 {%0,%1,%2,%3}, [%4];"
                 : "=r"(r[0]), "=r"(r[1]), "=r"(r[2]), "=r"(r[3]) : "r"(a));
}
__device__ __forceinline__ void ldsm4t(uint32_t a, uint32_t* r) {
    asm volatile("ldmatrix.sync.aligned.m8n8.x4.trans.shared.b16 {%0,%1,%2,%3}, [%4];"
                 : "=r"(r[0]), "=r"(r[1]), "=r"(r[2]), "=r"(r[3]) : "r"(a));
}
__device__ __forceinline__ void mma16816(float* c, const uint32_t* a,
                                         uint32_t b0, uint32_t b1) {
    asm volatile(
        "mma.sync.aligned.m16n8k16.row.col.f32.bf16.bf16.f32 "
        "{%0,%1,%2,%3}, {%4,%5,%6,%7}, {%8,%9}, {%0,%1,%2,%3};"
        : "+f"(c[0]), "+f"(c[1]), "+f"(c[2]), "+f"(c[3])
        : "r"(a[0]), "r"(a[1]), "r"(a[2]), "r"(a[3]), "r"(b0), "r"(b1));
}
__device__ __forceinline__ int sw128B(int row, int ch) {
    return (row << 7) + ((ch ^ (row & 7)) << 4);
}
// fast split: packed bf16x2 cvt
__device__ __forceinline__ void split2(float v0, float v1, uint32_t& ph, uint32_t& pl) {
    uint32_t h;
    asm("cvt.rn.bf16x2.f32 %0, %1, %2;" : "=r"(h) : "f"(v1), "f"(v0));
    float h0 = __uint_as_float(h << 16);
    float h1 = __uint_as_float(h & 0xffff0000u);
    uint32_t l;
    float r0 = v0 - h0, r1 = v1 - h1;
    asm("cvt.rn.bf16x2.f32 %0, %1, %2;" : "=r"(l) : "f"(r1), "f"(r0));
    ph = h; pl = l;
}
__device__ __forceinline__ uint32_t pack_bf16x2(float v0, float v1) {
    uint32_t h;
    asm("cvt.rn.bf16x2.f32 %0, %1, %2;" : "=r"(h) : "f"(v1), "f"(v0));
    return h;
}
// cp.async
__device__ __forceinline__ void cp16(uint32_t s, const void* g) {
    asm volatile("cp.async.cg.shared.global [%0], [%1], 16;" :: "r"(s), "l"(g));
}
#define CP_COMMIT() asm volatile("cp.async.commit_group;" ::: "memory")
#define CP_WAIT(n)  asm volatile("cp.async.wait_group %0;" :: "n"(n) : "memory")

// ---------------- fused split (fp32 -> bf16 hi/lo), float4-vectorized -------
__global__ void split_all(const float* __restrict__ x, const float* __restrict__ wq,
                          const float* __restrict__ wk, const float* __restrict__ wv,
                          const float* __restrict__ wo) {
    const int total4 = (TLEN * DMODEL + 4 * DMODEL * DMODEL) >> 2;
    for (int i4 = blockIdx.x * blockDim.x + threadIdx.x; i4 < total4;
         i4 += gridDim.x * blockDim.x) {
        int i = i4 << 2;
        const float* src;
        __nv_bfloat16 *hi, *lo;
        int off;
        if (i < TLEN * DMODEL) {
            src = x; hi = g_xh; lo = g_xl; off = i;
        } else {
            int j = i - TLEN * DMODEL;
            int w = j >> 20;
            off = j & ((1 << 20) - 1);
            src = (w == 0) ? wq : (w == 1) ? wk : (w == 2) ? wv : wo;
            hi = g_wh + ((size_t)w << 20);
            lo = g_wl + ((size_t)w << 20);
        }
        float4 v = *(const float4*)(src + off);
        uint32_t h0, l0, h1, l1;
        split2(v.x, v.y, h0, l0);
        split2(v.z, v.w, h1, l1);
        *(uint2*)(hi + off) = make_uint2(h0, h1);
        *(uint2*)(lo + off) = make_uint2(l0, l1);
    }
}

// ============================================================================
// Split-bf16 mma.sync GEMM v2: CTA tile 128x256, warp tile 64x64 (2x4 warps),
// KC=64, 2-stage double buffer (96KB/stage). LDSM/MMA ratio 0.67 (was 1.0).
// Per-element accumulation order identical to prior version.
// ============================================================================
#define GEMM_SMEM 196608
// stage layout: sAh +0 (16K) | sAl +16K | sWh +32K (32K) | sWl +64K -> 96K

__device__ __forceinline__ void gemm_prefetch(uint32_t sb, int s, int kc,
                                              const __nv_bfloat16* Ah, const __nv_bfloat16* Al,
                                              const __nv_bfloat16* Wh, const __nv_bfloat16* Wl,
                                              int m0, int n0, int tid) {
    uint32_t base = sb + s * 98304;
    #pragma unroll
    for (int p = 0; p < 4; p++) {             // A: 128 rows x 8 chunks
        int idx = p * 256 + tid;
        int r = idx >> 3, ch = idx & 7;
        size_t ga = (size_t)(m0 + r) * DMODEL + kc * 64 + ch * 8;
        uint32_t so = sw128B(r, ch);
        cp16(base + so,         Ah + ga);
        cp16(base + 16384 + so, Al + ga);
    }
    #pragma unroll
    for (int p = 0; p < 8; p++) {             // B: 256 rows x 8 chunks
        int idx = p * 256 + tid;
        int r = idx >> 3, ch = idx & 7;
        size_t gw = (size_t)(n0 + r) * DMODEL + kc * 64 + ch * 8;
        uint32_t so = sw128B(r, ch);
        cp16(base + 32768 + so, Wh + gw);
        cp16(base + 65536 + so, Wl + gw);
    }
}

__global__ __launch_bounds__(256, 1)
void gemm_bf16(int a_sel, int w_fixed, const float* __restrict__ bq,
               const float* __restrict__ bk, const float* __restrict__ bv,
               float* __restrict__ dout)
{
    extern __shared__ char sm[];
    uint32_t sb = sptr(sm);
    const int c_sel = (w_fixed < 0) ? (int)blockIdx.z : 3;
    const int w_idx = (w_fixed < 0) ? (int)blockIdx.z : w_fixed;
    const float* bias = (c_sel == 0) ? bq : (c_sel == 1) ? bk : (c_sel == 2) ? bv : nullptr;

    const __nv_bfloat16* Ah = a_sel ? g_oh : g_xh;
    const __nv_bfloat16* Al = a_sel ? g_ol : g_xl;
    const __nv_bfloat16* Wh = g_wh + (size_t)w_idx * DMODEL * DMODEL;
    const __nv_bfloat16* Wl = g_wl + (size_t)w_idx * DMODEL * DMODEL;

    const int tid = threadIdx.x;
    const int lane = tid & 31, wid = tid >> 5;
    const int g = lane >> 2, tg = lane & 3;
    const int wm = wid >> 2, wn = wid & 3;       // 2 x 4 warp grid
    const int m0 = blockIdx.y * 128, n0 = blockIdx.x * 256;

    float c[4][8][4];
    #pragma unroll
    for (int i = 0; i < 4; i++)
        #pragma unroll
        for (int j = 0; j < 8; j++)
            #pragma unroll
            for (int e = 0; e < 4; e++) c[i][j][e] = 0.f;

    gemm_prefetch(sb, 0, 0, Ah, Al, Wh, Wl, m0, n0, tid);
    CP_COMMIT();

    const int ar = lane & 15;
    const int br = ((lane >> 4) << 3) + (lane & 7);

    for (int kc = 0; kc < 16; kc++) {
        int s = kc & 1;
        if (kc + 1 < 16) {
            gemm_prefetch(sb, s ^ 1, kc + 1, Ah, Al, Wh, Wl, m0, n0, tid);
            CP_COMMIT();
            CP_WAIT(1);
        } else CP_WAIT(0);
        __syncthreads();

        uint32_t sAh = sb + s * 98304;
        uint32_t sAl = sAh + 16384;
        uint32_t sWh = sAh + 32768;
        uint32_t sWl = sAh + 65536;

        #pragma unroll
        for (int kt = 0; kt < 4; kt++) {
            uint32_t ah[4][4], al[4][4];
            const int ac = kt * 2 + (lane >> 4);
            #pragma unroll
            for (int mi = 0; mi < 4; mi++) {
                int r = wm * 64 + mi * 16 + ar;
                int off = sw128B(r, ac);
                ldsm4(sAh + off, ah[mi]);
                ldsm4(sAl + off, al[mi]);
            }
            uint32_t bh[4][4], bl[4][4];
            const int bc = kt * 2 + ((lane >> 3) & 1);
            #pragma unroll
            for (int pr = 0; pr < 4; pr++) {
                int r = wn * 64 + pr * 16 + br;
                int off = sw128B(r, bc);
                ldsm4(sWh + off, bh[pr]);
                ldsm4(sWl + off, bl[pr]);
            }
            #pragma unroll
            for (int mi = 0; mi < 4; mi++)
                #pragma unroll
                for (int ni = 0; ni < 8; ni++) {
                    uint32_t b0h = bh[ni >> 1][(ni & 1) * 2], b1h = bh[ni >> 1][(ni & 1) * 2 + 1];
                    uint32_t b0l = bl[ni >> 1][(ni & 1) * 2], b1l = bl[ni >> 1][(ni & 1) * 2 + 1];
                    mma16816(c[mi][ni], ah[mi], b0h, b1h);
                    mma16816(c[mi][ni], ah[mi], b0l, b1l);
                    mma16816(c[mi][ni], al[mi], b0h, b1h);
                }
        }
        __syncthreads();
    }

    __nv_bfloat16 *dsth = nullptr, *dstl = nullptr;
    if (c_sel == 0) { dsth = g_qh; dstl = g_ql; }
    else if (c_sel == 1) { dsth = g_kh; dstl = g_kl; }
    else if (c_sel == 2) { dsth = g_vh; dstl = g_vl; }

    #pragma unroll
    for (int mi = 0; mi < 4; mi++)
        #pragma unroll
        for (int ni = 0; ni < 8; ni++)
            #pragma unroll
            for (int inst = 0; inst < 2; inst++) {
                int m = m0 + wm * 64 + mi * 16 + inst * 8 + g;
                int n = n0 + wn * 64 + ni * 8 + 2 * tg;
                float b0 = bias ? bias[n] : 0.f;
                float b1 = bias ? bias[n + 1] : 0.f;
                float v0 = c[mi][ni][inst * 2] + b0;
                float v1 = c[mi][ni][inst * 2 + 1] + b1;
                if (c_sel < 3) {
                    uint32_t ph, pl;
                    split2(v0, v1, ph, pl);
                    size_t addr = ((size_t)(n >> 6) * TLEN + m) * HDIM + (n & 63);
                    *(uint32_t*)(dsth + addr) = ph;
                    *(uint32_t*)(dstl + addr) = pl;
                } else {
                    float2 r; r.x = v0; r.y = v1;
                    *(float2*)(dout + (size_t)m * DMODEL + n) = r;
                }
            }
}

// ============================================================================
// Warp-strip attention (R15 form, unchanged): 256 threads, warp owns 32 rows,
// 128-key tiles, 3-stage cp.async, prefetch-early, pipelined exp+PV.
// ============================================================================
#define AT_S(s)  ((s) * 65536)
#define ATTN_SMEM 196608
#define NT128    32

__device__ __forceinline__ void cp_tile128(uint32_t sdst, const __nv_bfloat16* g, int tid) {
    #pragma unroll
    for (int p = 0; p < 4; p++) {
        int idx = p * 256 + tid;
        int r = idx >> 3, ch = idx & 7;
        cp16(sdst + sw128B(r, ch), g + (size_t)r * HDIM + ch * 8);
    }
}
__device__ __forceinline__ void cp_tile256(uint32_t sdst, const __nv_bfloat16* g, int tid) {
    #pragma unroll
    for (int p = 0; p < 8; p++) {
        int idx = p * 256 + tid;
        int r = idx >> 3, ch = idx & 7;
        cp16(sdst + sw128B(r, ch), g + (size_t)r * HDIM + ch * 8);
    }
}

__global__ __launch_bounds__(256, 1)
void attn_kernel(float scaling)
{
    extern __shared__ char sm[];
    uint32_t sb = sptr(sm);
    const int tid = threadIdx.x;
    const int lane = tid & 31, wid = tid >> 5;
    const int tg = lane & 3;
    const int h = blockIdx.y;
    const int t0 = blockIdx.x * 256;

    const float GA = (float)12102203.17133801;
    const float GB = (float)1064986823.010288;
    const float GAS = __fmul_rn(GA, scaling);

    const __nv_bfloat16* Kh  = g_kh + (size_t)h * TLEN * HDIM;
    const __nv_bfloat16* Klp = g_kl + (size_t)h * TLEN * HDIM;
    const __nv_bfloat16* Vh  = g_vh + (size_t)h * TLEN * HDIM;
    const __nv_bfloat16* Vlp = g_vl + (size_t)h * TLEN * HDIM;

    const int ar = lane & 15;
    const int br = ((lane >> 4) << 3) + (lane & 7);

    cp_tile256(sb + 0,     g_qh + ((size_t)h * TLEN + t0) * HDIM, tid);
    cp_tile256(sb + 32768, g_ql + ((size_t)h * TLEN + t0) * HDIM, tid);
    CP_COMMIT();
    CP_WAIT(0);
    __syncthreads();
    uint32_t qh[2][4][4], ql[2][4][4];
    #pragma unroll
    for (int mi = 0; mi < 2; mi++)
        #pragma unroll
        for (int kt = 0; kt < 4; kt++) {
            int ac = kt * 2 + (lane >> 4);
            int r = wid * 32 + mi * 16 + ar;
            ldsm4(sb + 0     + sw128B(r, ac), qh[mi][kt]);
            ldsm4(sb + 32768 + sw128B(r, ac), ql[mi][kt]);
        }
    __syncthreads();

    cp_tile128(sb + AT_S(0), Kh, tid);
    CP_COMMIT();
    cp_tile128(sb + AT_S(1), Kh + (size_t)128 * HDIM, tid);
    CP_COMMIT();

    float rm[2][2];
    #pragma unroll
    for (int mi = 0; mi < 2; mi++) { rm[mi][0] = -3.402823466e38f; rm[mi][1] = -3.402823466e38f; }

    for (int st = 0; st < NT128; st++) {
        if (st < NT128 - 1) { CP_WAIT(1); } else { CP_WAIT(0); }
        __syncthreads();
        if (st + 2 < NT128) {
            cp_tile128(sb + AT_S((st + 2) % 3), Kh + (size_t)(st + 2) * 128 * HDIM, tid);
            CP_COMMIT();
        }
        uint32_t sKh = sb + AT_S(st % 3);

        #pragma unroll
        for (int n2 = 0; n2 < 8; n2++) {
            float c[2][2][4];
            #pragma unroll
            for (int mi = 0; mi < 2; mi++)
                #pragma unroll
                for (int u = 0; u < 2; u++)
                    #pragma unroll
                    for (int e = 0; e < 4; e++) c[mi][u][e] = 0.f;
            #pragma unroll
            for (int kt = 0; kt < 4; kt++) {
                uint32_t bh[4];
                ldsm4(sKh + sw128B(n2 * 16 + br, kt * 2 + ((lane >> 3) & 1)), bh);
                #pragma unroll
                for (int mi = 0; mi < 2; mi++) {
                    mma16816(c[mi][0], qh[mi][kt], bh[0], bh[1]);
                    mma16816(c[mi][1], qh[mi][kt], bh[2], bh[3]);
                }
            }
            #pragma unroll
            for (int mi = 0; mi < 2; mi++)
                #pragma unroll
                for (int u = 0; u < 2; u++) {
                    rm[mi][0] = fmaxf(rm[mi][0], fmaxf(c[mi][u][0], c[mi][u][1]));
                    rm[mi][1] = fmaxf(rm[mi][1], fmaxf(c[mi][u][2], c[mi][u][3]));
                }
        }
    }
    float cr[2][2];
    #pragma unroll
    for (int mi = 0; mi < 2; mi++)
        #pragma unroll
        for (int i = 0; i < 2; i++) {
            float v = rm[mi][i];
            v = fmaxf(v, __shfl_xor_sync(0xffffffff, v, 1));
            v = fmaxf(v, __shfl_xor_sync(0xffffffff, v, 2));
            float rmx = __fmul_rn(v, scaling);
            cr[mi][i] = __fmaf_rn(-GA, rmx, GB);
        }

    float o[2][8][4];
    #pragma unroll
    for (int mi = 0; mi < 2; mi++)
        #pragma unroll
        for (int i = 0; i < 8; i++)
            #pragma unroll
            for (int e = 0; e < 4; e++) o[mi][i][e] = 0.f;
    float rs[2][2] = {{0.f, 0.f}, {0.f, 0.f}};

    __syncthreads();
    #pragma unroll
    for (int t = 0; t < 2; t++) {
        size_t go = (size_t)t * 128 * HDIM;
        uint32_t d = sb + AT_S(t);
        cp_tile128(d,         Kh + go, tid);
        cp_tile128(d + 16384, Klp + go, tid);
        cp_tile128(d + 32768, Vh + go, tid);
        cp_tile128(d + 49152, Vlp + go, tid);
        CP_COMMIT();
    }

    for (int st = 0; st < NT128; st++) {
        if (st < NT128 - 1) { CP_WAIT(1); } else { CP_WAIT(0); }
        __syncthreads();
        if (st + 2 < NT128) {
            size_t go = (size_t)(st + 2) * 128 * HDIM;
            uint32_t d = sb + AT_S((st + 2) % 3);
            cp_tile128(d,         Kh + go, tid);
            cp_tile128(d + 16384, Klp + go, tid);
            cp_tile128(d + 32768, Vh + go, tid);
            cp_tile128(d + 49152, Vlp + go, tid);
            CP_COMMIT();
        }

        uint32_t base = sb + AT_S(st % 3);
        uint32_t sKh = base, sKl = base + 16384;
        uint32_t sVh = base + 32768, sVl = base + 49152;

        uint32_t ehp[2][4];

        #pragma unroll
        for (int n2 = 0; n2 < 8; n2++) {
            float c[2][2][4];
            #pragma unroll
            for (int mi = 0; mi < 2; mi++)
                #pragma unroll
                for (int u = 0; u < 2; u++)
                    #pragma unroll
                    for (int e = 0; e < 4; e++) c[mi][u][e] = 0.f;
            #pragma unroll
            for (int kt = 0; kt < 4; kt++) {
                uint32_t bh[4], bl[4];
                int soff = sw128B(n2 * 16 + br, kt * 2 + ((lane >> 3) & 1));
                ldsm4(sKh + soff, bh);
                ldsm4(sKl + soff, bl);
                #pragma unroll
                for (int mi = 0; mi < 2; mi++) {
                    mma16816(c[mi][0], qh[mi][kt], bh[0], bh[1]);
                    mma16816(c[mi][0], qh[mi][kt], bl[0], bl[1]);
                    mma16816(c[mi][0], ql[mi][kt], bh[0], bh[1]);
                    mma16816(c[mi][1], qh[mi][kt], bh[2], bh[3]);
                    mma16816(c[mi][1], qh[mi][kt], bl[2], bl[3]);
                    mma16816(c[mi][1], ql[mi][kt], bh[2], bh[3]);
                }
            }

            if (n2 > 0) {
                int pv = n2 - 1;
                #pragma unroll
                for (int dg = 0; dg < 4; dg++) {
                    uint32_t vh[4], vl[4];
                    int voff = sw128B(pv * 16 + ar, dg * 2 + (lane >> 4));
                    ldsm4t(sVh + voff, vh);
                    ldsm4t(sVl + voff, vl);
                    #pragma unroll
                    for (int mi = 0; mi < 2; mi++) {
                        mma16816(o[mi][dg * 2],     ehp[mi], vh[0], vh[1]);
                        mma16816(o[mi][dg * 2],     ehp[mi], vl[0], vl[1]);
                        mma16816(o[mi][dg * 2 + 1], ehp[mi], vh[2], vh[3]);
                        mma16816(o[mi][dg * 2 + 1], ehp[mi], vl[2], vl[3]);
                    }
                }
            }

            #pragma unroll
            for (int mi = 0; mi < 2; mi++) {
                float e00 = fexp_fused(c[mi][0][0], GAS, cr[mi][0]);
                float e01 = fexp_fused(c[mi][0][1], GAS, cr[mi][0]);
                float e02 = fexp_fused(c[mi][0][2], GAS, cr[mi][1]);
                float e03 = fexp_fused(c[mi][0][3], GAS, cr[mi][1]);
                float e10 = fexp_fused(c[mi][1][0], GAS, cr[mi][0]);
                float e11 = fexp_fused(c[mi][1][1], GAS, cr[mi][0]);
                float e12 = fexp_fused(c[mi][1][2], GAS, cr[mi][1]);
                float e13 = fexp_fused(c[mi][1][3], GAS, cr[mi][1]);
                rs[mi][0] += e00 + e01 + e10 + e11;
                rs[mi][1] += e02 + e03 + e12 + e13;
                ehp[mi][0] = pack_bf16x2(e00, e01);
                ehp[mi][1] = pack_bf16x2(e02, e03);
                ehp[mi][2] = pack_bf16x2(e10, e11);
                ehp[mi][3] = pack_bf16x2(e12, e13);
            }
        }

        #pragma unroll
        for (int dg = 0; dg < 4; dg++) {
            uint32_t vh[4], vl[4];
            int voff = sw128B(7 * 16 + ar, dg * 2 + (lane >> 4));
            ldsm4t(sVh + voff, vh);
            ldsm4t(sVl + voff, vl);
            #pragma unroll
            for (int mi = 0; mi < 2; mi++) {
                mma16816(o[mi][dg * 2],     ehp[mi], vh[0], vh[1]);
                mma16816(o[mi][dg * 2],     ehp[mi], vl[0], vl[1]);
                mma16816(o[mi][dg * 2 + 1], ehp[mi], vh[2], vh[3]);
                mma16816(o[mi][dg * 2 + 1], ehp[mi], vl[2], vl[3]);
            }
        }
    }

    #pragma unroll
    for (int mi = 0; mi < 2; mi++) {
        #pragma unroll
        for (int i = 0; i < 2; i++) {
            rs[mi][i] += __shfl_xor_sync(0xffffffff, rs[mi][i], 1);
            rs[mi][i] += __shfl_xor_sync(0xffffffff, rs[mi][i], 2);
        }
        float inv0 = 1.0f / rs[mi][0], inv1 = 1.0f / rs[mi][1];
        int r0 = t0 + wid * 32 + mi * 16 + (lane >> 2);
        #pragma unroll
        for (int dn = 0; dn < 8; dn++) {
            int d = h * HDIM + dn * 8 + 2 * tg;
            uint32_t ph, pl;
            split2(o[mi][dn][0] * inv0, o[mi][dn][1] * inv0, ph, pl);
            *(uint32_t*)(g_oh + (size_t)r0 * DMODEL + d) = ph;
            *(uint32_t*)(g_ol + (size_t)r0 * DMODEL + d) = pl;
            split2(o[mi][dn][2] * inv1, o[mi][dn][3] * inv1, ph, pl);
            *(uint32_t*)(g_oh + (size_t)(r0 + 8) * DMODEL + d) = ph;
            *(uint32_t*)(g_ol + (size_t)(r0 + 8) * DMODEL + d) = pl;
        }
    }
}

// ============================================================================
extern "C" void kernel_launch(void* const* d_in, const int* in_sizes, int n_in,
                              void* d_out, int out_size)
{
    const float* x  = (const float*)d_in[0];
    const float* Wq = (const float*)d_in[1];
    const float* bq = (const float*)d_in[2];
    const float* Wk = (const float*)d_in[3];
    const float* bk = (const float*)d_in[4];
    const float* Wv = (const float*)d_in[5];
    const float* bv = (const float*)d_in[6];
    const float* Wo = (const float*)d_in[7];
    float* out = (float*)d_out;

    // Quake q_rsqrt(64) exact fp32 step order
    float xq = 64.0f;
    int ib;
    memcpy(&ib, &xq, 4);
    ib = 0x5f3759df - (ib >> 1);
    float y;
    memcpy(&y, &ib, 4);
    float t = 0.5f * xq;
    t = t * y;
    t = t * y;
    float scaling = y * (1.5f - t);

    cudaFuncSetAttribute(gemm_bf16, cudaFuncAttributeMaxDynamicSharedMemorySize, GEMM_SMEM);
    cudaFuncSetAttribute(attn_kernel, cudaFuncAttributeMaxDynamicSharedMemorySize, ATTN_SMEM);

    split_all<<<2048, 256>>>(x, Wq, Wk, Wv, Wo);

    // fused QKV projections: CTA tile 128x256 -> grid (4, 32, 3)
    dim3 qkv_grid(DMODEL / 256, TLEN / 128, 3);
    gemm_bf16<<<qkv_grid, 256, GEMM_SMEM>>>(0, -1, bq, bk, bv, out);

    attn_kernel<<<dim3(TLEN / 256, NHEADS), 256, ATTN_SMEM>>>(scaling);

    // output projection
    dim3 o_grid(DMODEL / 256, TLEN / 128, 1);
    gemm_bf16<<<o_grid, 256, GEMM_SMEM>>>(1, 3, nullptr, nullptr, nullptr, out);
}

// round 17
// speedup vs baseline: 1.0154x; 1.0072x over previous
#include <cuda_runtime.h>
#include <cuda_bf16.h>
#include <cstring>
#include <cstdint>

#define TLEN   4096
#define DMODEL 1024
#define NHEADS 16
#define HDIM   64

// ---------------- device scratch ----------------
__device__ __nv_bfloat16 g_xh[TLEN * DMODEL], g_xl[TLEN * DMODEL];
__device__ __nv_bfloat16 g_wh[4 * DMODEL * DMODEL], g_wl[4 * DMODEL * DMODEL];
__device__ __nv_bfloat16 g_qh[NHEADS * TLEN * HDIM], g_ql[NHEADS * TLEN * HDIM];
__device__ __nv_bfloat16 g_kh[NHEADS * TLEN * HDIM], g_kl[NHEADS * TLEN * HDIM];
__device__ __nv_bfloat16 g_vh[NHEADS * TLEN * HDIM], g_vl[NHEADS * TLEN * HDIM];
__device__ __nv_bfloat16 g_oh[TLEN * DMODEL], g_ol[TLEN * DMODEL];

// ---------------- fastexp fused form ----------------
__device__ __forceinline__ float fexp_fused(float s, float gas, float crow) {
    float y = __fmaf_rn(s, gas, crow);
    int yi = (y < 8388608.0f) ? 0 : __float2int_rz(y);
    return __int_as_float(yi);
}

// ---------------- helpers ----------------
__device__ __forceinline__ uint32_t sptr(const void* p) {
    return (uint32_t)__cvta_generic_to_shared(p);
}
__device__ __forceinline__ void ldsm4(uint32_t a, uint32_t* r) {
    asm volatile("ldmatrix.sync.aligned.m8n8.x4.shared.b16 {%0,%1,%2,%3}, [%4];"
                 : "=r"(r[0]), "=r"(r[1]), "=r"(r[2]), "=r"(r[3]) : "r"(a));
}
__device__ __forceinline__ void ldsm4t(uint32_t a, uint32_t* r) {
    asm volatile("ldmatrix.sync.aligned.m8n8.x4.trans.shared.b16 {%0,%1,%2,%3}, [%4];"
                 : "=r"(r[0]), "=r"(r[1]), "=r"(r[2]), "=r"(r[3]) : "r"(a));
}
__device__ __forceinline__ void mma16816(float* c, const uint32_t* a,
                                         uint32_t b0, uint32_t b1) {
    asm volatile(
        "mma.sync.aligned.m16n8k16.row.col.f32.bf16.bf16.f32 "
        "{%0,%1,%2,%3}, {%4,%5,%6,%7}, {%8,%9}, {%0,%1,%2,%3};"
        : "+f"(c[0]), "+f"(c[1]), "+f"(c[2]), "+f"(c[3])
        : "r"(a[0]), "r"(a[1]), "r"(a[2]), "r"(a[3]), "r"(b0), "r"(b1));
}
__device__ __forceinline__ int sw128B(int row, int ch) {
    return (row << 7) + ((ch ^ (row & 7)) << 4);
}
// fast split: packed bf16x2 cvt
__device__ __forceinline__ void split2(float v0, float v1, uint32_t& ph, uint32_t& pl) {
    uint32_t h;
    asm("cvt.rn.bf16x2.f32 %0, %1, %2;" : "=r"(h) : "f"(v1), "f"(v0));
    float h0 = __uint_as_float(h << 16);
    float h1 = __uint_as_float(h & 0xffff0000u);
    uint32_t l;
    float r0 = v0 - h0, r1 = v1 - h1;
    asm("cvt.rn.bf16x2.f32 %0, %1, %2;" : "=r"(l) : "f"(r1), "f"(r0));
    ph = h; pl = l;
}
__device__ __forceinline__ uint32_t pack_bf16x2(float v0, float v1) {
    uint32_t h;
    asm("cvt.rn.bf16x2.f32 %0, %1, %2;" : "=r"(h) : "f"(v1), "f"(v0));
    return h;
}
// cp.async
__device__ __forceinline__ void cp16(uint32_t s, const void* g) {
    asm volatile("cp.async.cg.shared.global [%0], [%1], 16;" :: "r"(s), "l"(g));
}
#define CP_COMMIT() asm volatile("cp.async.commit_group;" ::: "memory")
#define CP_WAIT(n)  asm volatile("cp.async.wait_group %0;" :: "n"(n) : "memory")

// ---------------- fused split (fp32 -> bf16 hi/lo), float4-vectorized -------
__global__ void split_all(const float* __restrict__ x, const float* __restrict__ wq,
                          const float* __restrict__ wk, const float* __restrict__ wv,
                          const float* __restrict__ wo) {
    const int total4 = (TLEN * DMODEL + 4 * DMODEL * DMODEL) >> 2;
    for (int i4 = blockIdx.x * blockDim.x + threadIdx.x; i4 < total4;
         i4 += gridDim.x * blockDim.x) {
        int i = i4 << 2;
        const float* src;
        __nv_bfloat16 *hi, *lo;
        int off;
        if (i < TLEN * DMODEL) {
            src = x; hi = g_xh; lo = g_xl; off = i;
        } else {
            int j = i - TLEN * DMODEL;
            int w = j >> 20;
            off = j & ((1 << 20) - 1);
            src = (w == 0) ? wq : (w == 1) ? wk : (w == 2) ? wv : wo;
            hi = g_wh + ((size_t)w << 20);
            lo = g_wl + ((size_t)w << 20);
        }
        float4 v = *(const float4*)(src + off);
        uint32_t h0, l0, h1, l1;
        split2(v.x, v.y, h0, l0);
        split2(v.z, v.w, h1, l1);
        *(uint2*)(hi + off) = make_uint2(h0, h1);
        *(uint2*)(lo + off) = make_uint2(l0, l1);
    }
}

// ============================================================================
// Split-bf16 mma.sync GEMM — exact R14 winning form: 128x128 CTA tile, KC=64,
// 3-stage cp.async, ONE sync per chunk, prefetch AFTER compute.
// ============================================================================
#define GEMM_SMEM 196608

__device__ __forceinline__ void gemm_prefetch(uint32_t sb, int s, int kc,
                                              const __nv_bfloat16* Ah, const __nv_bfloat16* Al,
                                              const __nv_bfloat16* Wh, const __nv_bfloat16* Wl,
                                              int m0, int n0, int tid) {
    uint32_t base = sb + s * 65536;
    #pragma unroll
    for (int p = 0; p < 4; p++) {
        int idx = p * 256 + tid;
        int r = idx >> 3, ch = idx & 7;
        size_t ga = (size_t)(m0 + r) * DMODEL + kc * 64 + ch * 8;
        size_t gw = (size_t)(n0 + r) * DMODEL + kc * 64 + ch * 8;
        uint32_t so = sw128B(r, ch);
        cp16(base + so,          Ah + ga);
        cp16(base + 16384 + so,  Al + ga);
        cp16(base + 32768 + so,  Wh + gw);
        cp16(base + 49152 + so,  Wl + gw);
    }
}

__global__ __launch_bounds__(256, 1)
void gemm_bf16(int a_sel, int w_fixed, const float* __restrict__ bq,
               const float* __restrict__ bk, const float* __restrict__ bv,
               float* __restrict__ dout)
{
    extern __shared__ char sm[];
    uint32_t sb = sptr(sm);
    const int c_sel = (w_fixed < 0) ? (int)blockIdx.z : 3;
    const int w_idx = (w_fixed < 0) ? (int)blockIdx.z : w_fixed;
    const float* bias = (c_sel == 0) ? bq : (c_sel == 1) ? bk : (c_sel == 2) ? bv : nullptr;

    const __nv_bfloat16* Ah = a_sel ? g_oh : g_xh;
    const __nv_bfloat16* Al = a_sel ? g_ol : g_xl;
    const __nv_bfloat16* Wh = g_wh + (size_t)w_idx * DMODEL * DMODEL;
    const __nv_bfloat16* Wl = g_wl + (size_t)w_idx * DMODEL * DMODEL;

    const int tid = threadIdx.x;
    const int lane = tid & 31, wid = tid >> 5;
    const int g = lane >> 2, tg = lane & 3;
    const int wm = wid >> 2, wn = wid & 3;
    const int m0 = blockIdx.y * 128, n0 = blockIdx.x * 128;

    float c[4][4][4];
    #pragma unroll
    for (int i = 0; i < 4; i++)
        #pragma unroll
        for (int j = 0; j < 4; j++)
            #pragma unroll
            for (int e = 0; e < 4; e++) c[i][j][e] = 0.f;

    gemm_prefetch(sb, 0, 0, Ah, Al, Wh, Wl, m0, n0, tid);
    CP_COMMIT();
    gemm_prefetch(sb, 1, 1, Ah, Al, Wh, Wl, m0, n0, tid);
    CP_COMMIT();

    const int ar = lane & 15;
    const int br = ((lane >> 4) << 3) + (lane & 7);

    for (int kc = 0; kc < 16; kc++) {
        int s = kc % 3;
        if (kc < 15) { CP_WAIT(1); } else { CP_WAIT(0); }
        __syncthreads();

        uint32_t sAh = sb + s * 65536;
        uint32_t sAl = sAh + 16384;
        uint32_t sWh = sAh + 32768;
        uint32_t sWl = sAh + 49152;

        #pragma unroll
        for (int kt = 0; kt < 4; kt++) {
            uint32_t ah[4][4], al[4][4];
            const int ac = kt * 2 + (lane >> 4);
            #pragma unroll
            for (int mi = 0; mi < 4; mi++) {
                int r = wm * 64 + mi * 16 + ar;
                int off = sw128B(r, ac);
                ldsm4(sAh + off, ah[mi]);
                ldsm4(sAl + off, al[mi]);
            }
            uint32_t bh[2][4], bl[2][4];
            const int bc = kt * 2 + ((lane >> 3) & 1);
            #pragma unroll
            for (int pr = 0; pr < 2; pr++) {
                int r = wn * 32 + pr * 16 + br;
                int off = sw128B(r, bc);
                ldsm4(sWh + off, bh[pr]);
                ldsm4(sWl + off, bl[pr]);
            }
            #pragma unroll
            for (int mi = 0; mi < 4; mi++)
                #pragma unroll
                for (int ni = 0; ni < 4; ni++) {
                    uint32_t b0h = bh[ni >> 1][(ni & 1) * 2], b1h = bh[ni >> 1][(ni & 1) * 2 + 1];
                    uint32_t b0l = bl[ni >> 1][(ni & 1) * 2], b1l = bl[ni >> 1][(ni & 1) * 2 + 1];
                    mma16816(c[mi][ni], ah[mi], b0h, b1h);
                    mma16816(c[mi][ni], ah[mi], b0l, b1l);
                    mma16816(c[mi][ni], al[mi], b0h, b1h);
                }
        }

        if (kc + 2 < 16) {
            gemm_prefetch(sb, (kc + 2) % 3, kc + 2, Ah, Al, Wh, Wl, m0, n0, tid);
            CP_COMMIT();
        }
    }

    __nv_bfloat16 *dsth = nullptr, *dstl = nullptr;
    if (c_sel == 0) { dsth = g_qh; dstl = g_ql; }
    else if (c_sel == 1) { dsth = g_kh; dstl = g_kl; }
    else if (c_sel == 2) { dsth = g_vh; dstl = g_vl; }

    #pragma unroll
    for (int mi = 0; mi < 4; mi++)
        #pragma unroll
        for (int ni = 0; ni < 4; ni++)
            #pragma unroll
            for (int inst = 0; inst < 2; inst++) {
                int m = m0 + wm * 64 + mi * 16 + inst * 8 + g;
                int n = n0 + wn * 32 + ni * 8 + 2 * tg;
                float b0 = bias ? bias[n] : 0.f;
                float b1 = bias ? bias[n + 1] : 0.f;
                float v0 = c[mi][ni][inst * 2] + b0;
                float v1 = c[mi][ni][inst * 2 + 1] + b1;
                if (c_sel < 3) {
                    uint32_t ph, pl;
                    split2(v0, v1, ph, pl);
                    size_t addr = ((size_t)(n >> 6) * TLEN + m) * HDIM + (n & 63);
                    *(uint32_t*)(dsth + addr) = ph;
                    *(uint32_t*)(dstl + addr) = pl;
                } else {
                    float2 r; r.x = v0; r.y = v1;
                    *(float2*)(dout + (size_t)m * DMODEL + n) = r;
                }
            }
}

// ============================================================================
// Warp-strip attention (R15/R16 form): 256 threads, warp owns 32 q-rows,
// 128-key tiles, 3-stage cp.async, prefetch-early, pipelined exp+PV.
// ============================================================================
#define AT_S(s)  ((s) * 65536)
#define ATTN_SMEM 196608
#define NT128    32

__device__ __forceinline__ void cp_tile128(uint32_t sdst, const __nv_bfloat16* g, int tid) {
    #pragma unroll
    for (int p = 0; p < 4; p++) {
        int idx = p * 256 + tid;
        int r = idx >> 3, ch = idx & 7;
        cp16(sdst + sw128B(r, ch), g + (size_t)r * HDIM + ch * 8);
    }
}
__device__ __forceinline__ void cp_tile256(uint32_t sdst, const __nv_bfloat16* g, int tid) {
    #pragma unroll
    for (int p = 0; p < 8; p++) {
        int idx = p * 256 + tid;
        int r = idx >> 3, ch = idx & 7;
        cp16(sdst + sw128B(r, ch), g + (size_t)r * HDIM + ch * 8);
    }
}

__global__ __launch_bounds__(256, 1)
void attn_kernel(float scaling)
{
    extern __shared__ char sm[];
    uint32_t sb = sptr(sm);
    const int tid = threadIdx.x;
    const int lane = tid & 31, wid = tid >> 5;
    const int tg = lane & 3;
    const int h = blockIdx.y;
    const int t0 = blockIdx.x * 256;

    const float GA = (float)12102203.17133801;
    const float GB = (float)1064986823.010288;
    const float GAS = __fmul_rn(GA, scaling);

    const __nv_bfloat16* Kh  = g_kh + (size_t)h * TLEN * HDIM;
    const __nv_bfloat16* Klp = g_kl + (size_t)h * TLEN * HDIM;
    const __nv_bfloat16* Vh  = g_vh + (size_t)h * TLEN * HDIM;
    const __nv_bfloat16* Vlp = g_vl + (size_t)h * TLEN * HDIM;

    const int ar = lane & 15;
    const int br = ((lane >> 4) << 3) + (lane & 7);

    cp_tile256(sb + 0,     g_qh + ((size_t)h * TLEN + t0) * HDIM, tid);
    cp_tile256(sb + 32768, g_ql + ((size_t)h * TLEN + t0) * HDIM, tid);
    CP_COMMIT();
    CP_WAIT(0);
    __syncthreads();
    uint32_t qh[2][4][4], ql[2][4][4];
    #pragma unroll
    for (int mi = 0; mi < 2; mi++)
        #pragma unroll
        for (int kt = 0; kt < 4; kt++) {
            int ac = kt * 2 + (lane >> 4);
            int r = wid * 32 + mi * 16 + ar;
            ldsm4(sb + 0     + sw128B(r, ac), qh[mi][kt]);
            ldsm4(sb + 32768 + sw128B(r, ac), ql[mi][kt]);
        }
    __syncthreads();

    cp_tile128(sb + AT_S(0), Kh, tid);
    CP_COMMIT();
    cp_tile128(sb + AT_S(1), Kh + (size_t)128 * HDIM, tid);
    CP_COMMIT();

    float rm[2][2];
    #pragma unroll
    for (int mi = 0; mi < 2; mi++) { rm[mi][0] = -3.402823466e38f; rm[mi][1] = -3.402823466e38f; }

    for (int st = 0; st < NT128; st++) {
        if (st < NT128 - 1) { CP_WAIT(1); } else { CP_WAIT(0); }
        __syncthreads();
        if (st + 2 < NT128) {
            cp_tile128(sb + AT_S((st + 2) % 3), Kh + (size_t)(st + 2) * 128 * HDIM, tid);
            CP_COMMIT();
        }
        uint32_t sKh = sb + AT_S(st % 3);

        #pragma unroll
        for (int n2 = 0; n2 < 8; n2++) {
            float c[2][2][4];
            #pragma unroll
            for (int mi = 0; mi < 2; mi++)
                #pragma unroll
                for (int u = 0; u < 2; u++)
                    #pragma unroll
                    for (int e = 0; e < 4; e++) c[mi][u][e] = 0.f;
            #pragma unroll
            for (int kt = 0; kt < 4; kt++) {
                uint32_t bh[4];
                ldsm4(sKh + sw128B(n2 * 16 + br, kt * 2 + ((lane >> 3) & 1)), bh);
                #pragma unroll
                for (int mi = 0; mi < 2; mi++) {
                    mma16816(c[mi][0], qh[mi][kt], bh[0], bh[1]);
                    mma16816(c[mi][1], qh[mi][kt], bh[2], bh[3]);
                }
            }
            #pragma unroll
            for (int mi = 0; mi < 2; mi++)
                #pragma unroll
                for (int u = 0; u < 2; u++) {
                    rm[mi][0] = fmaxf(rm[mi][0], fmaxf(c[mi][u][0], c[mi][u][1]));
                    rm[mi][1] = fmaxf(rm[mi][1], fmaxf(c[mi][u][2], c[mi][u][3]));
                }
        }
    }
    float cr[2][2];
    #pragma unroll
    for (int mi = 0; mi < 2; mi++)
        #pragma unroll
        for (int i = 0; i < 2; i++) {
            float v = rm[mi][i];
            v = fmaxf(v, __shfl_xor_sync(0xffffffff, v, 1));
            v = fmaxf(v, __shfl_xor_sync(0xffffffff, v, 2));
            float rmx = __fmul_rn(v, scaling);
            cr[mi][i] = __fmaf_rn(-GA, rmx, GB);
        }

    float o[2][8][4];
    #pragma unroll
    for (int mi = 0; mi < 2; mi++)
        #pragma unroll
        for (int i = 0; i < 8; i++)
            #pragma unroll
            for (int e = 0; e < 4; e++) o[mi][i][e] = 0.f;
    float rs[2][2] = {{0.f, 0.f}, {0.f, 0.f}};

    __syncthreads();
    #pragma unroll
    for (int t = 0; t < 2; t++) {
        size_t go = (size_t)t * 128 * HDIM;
        uint32_t d = sb + AT_S(t);
        cp_tile128(d,         Kh + go, tid);
        cp_tile128(d + 16384, Klp + go, tid);
        cp_tile128(d + 32768, Vh + go, tid);
        cp_tile128(d + 49152, Vlp + go, tid);
        CP_COMMIT();
    }

    for (int st = 0; st < NT128; st++) {
        if (st < NT128 - 1) { CP_WAIT(1); } else { CP_WAIT(0); }
        __syncthreads();
        if (st + 2 < NT128) {
            size_t go = (size_t)(st + 2) * 128 * HDIM;
            uint32_t d = sb + AT_S((st + 2) % 3);
            cp_tile128(d,         Kh + go, tid);
            cp_tile128(d + 16384, Klp + go, tid);
            cp_tile128(d + 32768, Vh + go, tid);
            cp_tile128(d + 49152, Vlp + go, tid);
            CP_COMMIT();
        }

        uint32_t base = sb + AT_S(st % 3);
        uint32_t sKh = base, sKl = base + 16384;
        uint32_t sVh = base + 32768, sVl = base + 49152;

        uint32_t ehp[2][4];

        #pragma unroll
        for (int n2 = 0; n2 < 8; n2++) {
            float c[2][2][4];
            #pragma unroll
            for (int mi = 0; mi < 2; mi++)
                #pragma unroll
                for (int u = 0; u < 2; u++)
                    #pragma unroll
                    for (int e = 0; e < 4; e++) c[mi][u][e] = 0.f;
            #pragma unroll
            for (int kt = 0; kt < 4; kt++) {
                uint32_t bh[4], bl[4];
                int soff = sw128B(n2 * 16 + br, kt * 2 + ((lane >> 3) & 1));
                ldsm4(sKh + soff, bh);
                ldsm4(sKl + soff, bl);
                #pragma unroll
                for (int mi = 0; mi < 2; mi++) {
                    mma16816(c[mi][0], qh[mi][kt], bh[0], bh[1]);
                    mma16816(c[mi][0], qh[mi][kt], bl[0], bl[1]);
                    mma16816(c[mi][0], ql[mi][kt], bh[0], bh[1]);
                    mma16816(c[mi][1], qh[mi][kt], bh[2], bh[3]);
                    mma16816(c[mi][1], qh[mi][kt], bl[2], bl[3]);
                    mma16816(c[mi][1], ql[mi][kt], bh[2], bh[3]);
                }
            }

            if (n2 > 0) {
                int pv = n2 - 1;
                #pragma unroll
                for (int dg = 0; dg < 4; dg++) {
                    uint32_t vh[4], vl[4];
                    int voff = sw128B(pv * 16 + ar, dg * 2 + (lane >> 4));
                    ldsm4t(sVh + voff, vh);
                    ldsm4t(sVl + voff, vl);
                    #pragma unroll
                    for (int mi = 0; mi < 2; mi++) {
                        mma16816(o[mi][dg * 2],     ehp[mi], vh[0], vh[1]);
                        mma16816(o[mi][dg * 2],     ehp[mi], vl[0], vl[1]);
                        mma16816(o[mi][dg * 2 + 1], ehp[mi], vh[2], vh[3]);
                        mma16816(o[mi][dg * 2 + 1], ehp[mi], vl[2], vl[3]);
                    }
                }
            }

            #pragma unroll
            for (int mi = 0; mi < 2; mi++) {
                float e00 = fexp_fused(c[mi][0][0], GAS, cr[mi][0]);
                float e01 = fexp_fused(c[mi][0][1], GAS, cr[mi][0]);
                float e02 = fexp_fused(c[mi][0][2], GAS, cr[mi][1]);
                float e03 = fexp_fused(c[mi][0][3], GAS, cr[mi][1]);
                float e10 = fexp_fused(c[mi][1][0], GAS, cr[mi][0]);
                float e11 = fexp_fused(c[mi][1][1], GAS, cr[mi][0]);
                float e12 = fexp_fused(c[mi][1][2], GAS, cr[mi][1]);
                float e13 = fexp_fused(c[mi][1][3], GAS, cr[mi][1]);
                rs[mi][0] += e00 + e01 + e10 + e11;
                rs[mi][1] += e02 + e03 + e12 + e13;
                ehp[mi][0] = pack_bf16x2(e00, e01);
                ehp[mi][1] = pack_bf16x2(e02, e03);
                ehp[mi][2] = pack_bf16x2(e10, e11);
                ehp[mi][3] = pack_bf16x2(e12, e13);
            }
        }

        #pragma unroll
        for (int dg = 0; dg < 4; dg++) {
            uint32_t vh[4], vl[4];
            int voff = sw128B(7 * 16 + ar, dg * 2 + (lane >> 4));
            ldsm4t(sVh + voff, vh);
            ldsm4t(sVl + voff, vl);
            #pragma unroll
            for (int mi = 0; mi < 2; mi++) {
                mma16816(o[mi][dg * 2],     ehp[mi], vh[0], vh[1]);
                mma16816(o[mi][dg * 2],     ehp[mi], vl[0], vl[1]);
                mma16816(o[mi][dg * 2 + 1], ehp[mi], vh[2], vh[3]);
                mma16816(o[mi][dg * 2 + 1], ehp[mi], vl[2], vl[3]);
            }
        }
    }

    #pragma unroll
    for (int mi = 0; mi < 2; mi++) {
        #pragma unroll
        for (int i = 0; i < 2; i++) {
            rs[mi][i] += __shfl_xor_sync(0xffffffff, rs[mi][i], 1);
            rs[mi][i] += __shfl_xor_sync(0xffffffff, rs[mi][i], 2);
        }
        float inv0 = 1.0f / rs[mi][0], inv1 = 1.0f / rs[mi][1];
        int r0 = t0 + wid * 32 + mi * 16 + (lane >> 2);
        #pragma unroll
        for (int dn = 0; dn < 8; dn++) {
            int d = h * HDIM + dn * 8 + 2 * tg;
            uint32_t ph, pl;
            split2(o[mi][dn][0] * inv0, o[mi][dn][1] * inv0, ph, pl);
            *(uint32_t*)(g_oh + (size_t)r0 * DMODEL + d) = ph;
            *(uint32_t*)(g_ol + (size_t)r0 * DMODEL + d) = pl;
            split2(o[mi][dn][2] * inv1, o[mi][dn][3] * inv1, ph, pl);
            *(uint32_t*)(g_oh + (size_t)(r0 + 8) * DMODEL + d) = ph;
            *(uint32_t*)(g_ol + (size_t)(r0 + 8) * DMODEL + d) = pl;
        }
    }
}

// ============================================================================
extern "C" void kernel_launch(void* const* d_in, const int* in_sizes, int n_in,
                              void* d_out, int out_size)
{
    const float* x  = (const float*)d_in[0];
    const float* Wq = (const float*)d_in[1];
    const float* bq = (const float*)d_in[2];
    const float* Wk = (const float*)d_in[3];
    const float* bk = (const float*)d_in[4];
    const float* Wv = (const float*)d_in[5];
    const float* bv = (const float*)d_in[6];
    const float* Wo = (const float*)d_in[7];
    float* out = (float*)d_out;

    // Quake q_rsqrt(64) exact fp32 step order
    float xq = 64.0f;
    int ib;
    memcpy(&ib, &xq, 4);
    ib = 0x5f3759df - (ib >> 1);
    float y;
    memcpy(&y, &ib, 4);
    float t = 0.5f * xq;
    t = t * y;
    t = t * y;
    float scaling = y * (1.5f - t);

    cudaFuncSetAttribute(gemm_bf16, cudaFuncAttributeMaxDynamicSharedMemorySize, GEMM_SMEM);
    cudaFuncSetAttribute(attn_kernel, cudaFuncAttributeMaxDynamicSharedMemorySize, ATTN_SMEM);

    split_all<<<2048, 256>>>(x, Wq, Wk, Wv, Wo);

    dim3 qkv_grid(DMODEL / 128, TLEN / 128, 3);
    gemm_bf16<<<qkv_grid, 256, GEMM_SMEM>>>(0, -1, bq, bk, bv, out);

    attn_kernel<<<dim3(TLEN / 256, NHEADS), 256, ATTN_SMEM>>>(scaling);

    dim3 o_grid(DMODEL / 128, TLEN / 128, 1);
    gemm_bf16<<<o_grid, 256, GEMM_SMEM>>>(1, 3, nullptr, nullptr, nullptr, out);
}